// round 5
// baseline (speedup 1.0000x reference)
#include <cuda_runtime.h>
#include <math.h>

// MaxNormPooling2D: quaternion max-norm 2x2 pooling, stride 2, VALID.
// Inputs: x0..x3 each (B=16, H=128, W=128, C=64) fp32, NHWC.
// Output: concatenated (out0, out1, out2, out3), each (16, 64, 64, 64) fp32.
//
// Per (b, ho, wo, c): over the 4 window positions (dh,dw) in row-major
// order, pick the position with max sqrt(x0^2+x1^2+x2^2+x3^2) (first-max
// tie-break) and emit that position's 4 components.
//
// R4: float2-per-thread (halves register footprint vs float4 -> higher
// occupancy for a latency/MLP-limited stream) + __ldcs/__stcs streaming
// cache hints (320MB streams through 126MB L2 once; evict-first).

#define B_  16
#define H_  128
#define W_  128
#define C_  64
#define HO_ 64
#define WO_ 64

// float2 granularity: 32 float2 groups per pixel channel dim (C=64/2)
#define C2_ 32
// total threads = B * HO * WO * C2 = 16*64*64*32 = 2,097,152
#define NTHREADS_TOTAL (B_ * HO_ * WO_ * C2_)

// per-component output size in float2 units: 16*64*64*64/2 = 2,097,152
#define OUT_COMP_F2 (B_ * HO_ * WO_ * C_ / 2)

__global__ __launch_bounds__(256) void maxnorm_pool_kernel(
    const float2* __restrict__ x0,
    const float2* __restrict__ x1,
    const float2* __restrict__ x2,
    const float2* __restrict__ x3,
    float2* __restrict__ out)
{
    int t = blockIdx.x * blockDim.x + threadIdx.x;
    if (t >= NTHREADS_TOTAL) return;

    int c2  = t & (C2_ - 1);
    int pix = t >> 5;             // b*HO*WO + ho*WO + wo
    int wo  = pix & (WO_ - 1);
    int ho  = (pix >> 6) & (HO_ - 1);
    int b   = pix >> 12;

    int h0 = ho << 1;
    int w0 = wo << 1;

    // input index in float2 units: ((b*H + h)*W + w)*C2 + c2
    // window positions in row-major order: (0,0),(0,1),(1,0),(1,1)
    int base = ((b * H_ + h0) * W_ + w0) * C2_ + c2;
    int off[4];
    off[0] = base;
    off[1] = base + C2_;          // dw=1
    off[2] = base + W_ * C2_;     // dh=1
    off[3] = base + W_ * C2_ + C2_;

    // best norm per lane (norms >= 0, so -1 guarantees p=0 wins first ->
    // first-max tie-break like TF/argmax)
    float2 bn = make_float2(-1.f, -1.f);
    float2 o0, o1, o2, o3;

#pragma unroll
    for (int p = 0; p < 4; ++p) {
        float2 a0 = __ldcs(x0 + off[p]);
        float2 a1 = __ldcs(x1 + off[p]);
        float2 a2 = __ldcs(x2 + off[p]);
        float2 a3 = __ldcs(x3 + off[p]);

        // sequential sum order x0^2 + x1^2 + x2^2 + x3^2, then sqrt —
        // matches the reference's comparison domain for tie behavior.
        float nx = sqrtf(a0.x * a0.x + a1.x * a1.x + a2.x * a2.x + a3.x * a3.x);
        float ny = sqrtf(a0.y * a0.y + a1.y * a1.y + a2.y * a2.y + a3.y * a3.y);

        if (nx > bn.x) { bn.x = nx; o0.x = a0.x; o1.x = a1.x; o2.x = a2.x; o3.x = a3.x; }
        if (ny > bn.y) { bn.y = ny; o0.y = a0.y; o1.y = a1.y; o2.y = a2.y; o3.y = a3.y; }
    }

    int obase = pix * C2_ + c2;   // within one component, float2 units
    __stcs(out + obase,                   o0);
    __stcs(out + obase +     OUT_COMP_F2, o1);
    __stcs(out + obase + 2 * OUT_COMP_F2, o2);
    __stcs(out + obase + 3 * OUT_COMP_F2, o3);
}

extern "C" void kernel_launch(void* const* d_in, const int* in_sizes, int n_in,
                              void* d_out, int out_size)
{
    const float2* x0 = (const float2*)d_in[0];
    const float2* x1 = (const float2*)d_in[1];
    const float2* x2 = (const float2*)d_in[2];
    const float2* x3 = (const float2*)d_in[3];
    float2* out = (float2*)d_out;

    const int threads = 256;
    const int blocks  = NTHREADS_TOTAL / threads;  // 8192
    maxnorm_pool_kernel<<<blocks, threads>>>(x0, x1, x2, x3, out);
}

// round 6
// speedup vs baseline: 1.0365x; 1.0365x over previous
#include <cuda_runtime.h>
#include <math.h>

// MaxNormPooling2D: quaternion max-norm 2x2 pooling, stride 2, VALID.
// Inputs: x0..x3 each (B=16, H=128, W=128, C=64) fp32, NHWC.
// Output: concatenated (out0..out3), each (16, 64, 64, 64) fp32.
//
// R5: 256-bit global loads/stores (ld/st.global.v8.f32, sm_100+) — halve
// memory instruction count, double bytes/request, denser DRAM bursts.
// Each thread handles 8 consecutive channels (c8 group) of one output pixel.

#define B_  16
#define H_  128
#define W_  128
#define C_  64
#define HO_ 64
#define WO_ 64

#define C8_ 8   // 8 groups of 8 floats per pixel channel dim
// total threads = 16*64*64*8 = 524,288
#define NTHREADS_TOTAL (B_ * HO_ * WO_ * C8_)
// per-component output size in floats: 16*64*64*64 = 4,194,304
#define OUT_COMP_F (B_ * HO_ * WO_ * C_)

__device__ __forceinline__ void ldg_v8(const float* __restrict__ p, float* v)
{
    asm volatile("ld.global.v8.f32 {%0,%1,%2,%3,%4,%5,%6,%7}, [%8];"
                 : "=f"(v[0]), "=f"(v[1]), "=f"(v[2]), "=f"(v[3]),
                   "=f"(v[4]), "=f"(v[5]), "=f"(v[6]), "=f"(v[7])
                 : "l"(p));
}

__device__ __forceinline__ void stg_v8(float* __restrict__ p, const float* v)
{
    asm volatile("st.global.v8.f32 [%0], {%1,%2,%3,%4,%5,%6,%7,%8};"
                 :: "l"(p),
                    "f"(v[0]), "f"(v[1]), "f"(v[2]), "f"(v[3]),
                    "f"(v[4]), "f"(v[5]), "f"(v[6]), "f"(v[7])
                 : "memory");
}

__global__ __launch_bounds__(256) void maxnorm_pool_kernel(
    const float* __restrict__ x0,
    const float* __restrict__ x1,
    const float* __restrict__ x2,
    const float* __restrict__ x3,
    float* __restrict__ out)
{
    int t = blockIdx.x * blockDim.x + threadIdx.x;
    if (t >= NTHREADS_TOTAL) return;

    int c8  = t & (C8_ - 1);
    int pix = t >> 3;             // b*HO*WO + ho*WO + wo
    int wo  = pix & (WO_ - 1);
    int ho  = (pix >> 6) & (HO_ - 1);
    int b   = pix >> 12;

    int h0 = ho << 1;
    int w0 = wo << 1;

    // float-unit index of this thread's 8-channel chunk at window origin
    int base = ((b * H_ + h0) * W_ + w0) * C_ + (c8 << 3);
    // window positions in row-major order: (0,0),(0,1),(1,0),(1,1)
    int off[4];
    off[0] = base;
    off[1] = base + C_;           // dw=1
    off[2] = base + W_ * C_;      // dh=1
    off[3] = base + W_ * C_ + C_;

    // best norm per channel lane (norms >= 0; -1 => p=0 wins first,
    // first-max tie-break like TF/argmax)
    float bn[8];
    float o0[8], o1[8], o2[8], o3[8];
#pragma unroll
    for (int i = 0; i < 8; ++i) bn[i] = -1.f;

#pragma unroll
    for (int p = 0; p < 4; ++p) {
        float a0[8], a1[8], a2[8], a3[8];
        ldg_v8(x0 + off[p], a0);
        ldg_v8(x1 + off[p], a1);
        ldg_v8(x2 + off[p], a2);
        ldg_v8(x3 + off[p], a3);

#pragma unroll
        for (int i = 0; i < 8; ++i) {
            // sequential sum order x0^2 + x1^2 + x2^2 + x3^2, then sqrt —
            // matches the reference's comparison domain for tie behavior.
            float n = sqrtf(a0[i] * a0[i] + a1[i] * a1[i] +
                            a2[i] * a2[i] + a3[i] * a3[i]);
            if (n > bn[i]) {
                bn[i] = n;
                o0[i] = a0[i]; o1[i] = a1[i];
                o2[i] = a2[i]; o3[i] = a3[i];
            }
        }
    }

    int obase = pix * C_ + (c8 << 3);   // within one component, float units
    stg_v8(out + obase,                  o0);
    stg_v8(out + obase +     OUT_COMP_F, o1);
    stg_v8(out + obase + 2 * OUT_COMP_F, o2);
    stg_v8(out + obase + 3 * OUT_COMP_F, o3);
}

extern "C" void kernel_launch(void* const* d_in, const int* in_sizes, int n_in,
                              void* d_out, int out_size)
{
    const float* x0 = (const float*)d_in[0];
    const float* x1 = (const float*)d_in[1];
    const float* x2 = (const float*)d_in[2];
    const float* x3 = (const float*)d_in[3];
    float* out = (float*)d_out;

    const int threads = 256;
    const int blocks  = NTHREADS_TOTAL / threads;  // 2048
    maxnorm_pool_kernel<<<blocks, threads>>>(x0, x1, x2, x3, out);
}